// round 16
// baseline (speedup 1.0000x reference)
#include <cuda_runtime.h>
#include <cuda_fp16.h>
#include <math.h>
#include <stdint.h>

#define BATCH 32
#define HH 32
#define WW_ 32
#define L 1024
#define DIM 384
#define NH 12
#define HD 32
#define WS 7
#define NWIN 800
#define NTOK 49
#define TOKENS (NWIN * NTOK)   // 39200
#define MPAD 39296
#define BL (BATCH * L)         // 32768
#define FFN (4 * DIM)          // 1536
#define EPSV 1e-5f

// ---------------- scratch ----------------
__device__ __half g_xn[(size_t)MPAD * DIM];
__device__ __half g_qkv[(size_t)MPAD * 3 * DIM];
__device__ __half g_ao[(size_t)MPAD * DIM];
__device__ float  g_xa[(size_t)BL * DIM];
__device__ float  g_xb[(size_t)BL * DIM];
__device__ __half g_xn2[(size_t)BL * DIM];
__device__ __half g_h[(size_t)BL * FFN];
__device__ __half g_wqh[(size_t)3 * DIM * DIM];
__device__ __half g_wph[(size_t)DIM * DIM];
__device__ __half g_w1h[(size_t)FFN * DIM];
__device__ __half g_w2h[(size_t)DIM * FFN];
__device__ float  g_biasf[(size_t)NH * NTOK * NTOK];

// ================= common helpers =================
__device__ __forceinline__ uint32_t s2u(const void* p) {
    uint32_t a;
    asm("{ .reg .u64 t; cvta.to.shared.u64 t, %1; cvt.u32.u64 %0, t; }" : "=r"(a) : "l"(p));
    return a;
}
__device__ __forceinline__ void cp_async16(uint32_t dst, const void* src) {
    asm volatile("cp.async.cg.shared.global [%0], [%1], 16;" :: "r"(dst), "l"(src) : "memory");
}
__device__ __forceinline__ void cp_commit() {
    asm volatile("cp.async.commit_group;" ::: "memory");
}
template <int N>
__device__ __forceinline__ void cp_wait() {
    asm volatile("cp.async.wait_group %0;" :: "n"(N) : "memory");
}
__device__ __forceinline__ uint32_t sw128(uint32_t byte_off) {
    return byte_off ^ ((byte_off >> 3) & 0x70u);
}
__device__ __forceinline__ void ldsm_x4(uint32_t* r, uint32_t addr) {
    asm volatile("ldmatrix.sync.aligned.m8n8.x4.shared.b16 {%0,%1,%2,%3}, [%4];"
                 : "=r"(r[0]), "=r"(r[1]), "=r"(r[2]), "=r"(r[3]) : "r"(addr));
}
__device__ __forceinline__ void mma_f16(float* c, const uint32_t* a, const uint32_t* b) {
    asm volatile("mma.sync.aligned.m16n8k16.row.col.f32.f16.f16.f32 "
                 "{%0,%1,%2,%3}, {%4,%5,%6,%7}, {%8,%9}, {%0,%1,%2,%3};"
                 : "+f"(c[0]), "+f"(c[1]), "+f"(c[2]), "+f"(c[3])
                 : "r"(a[0]), "r"(a[1]), "r"(a[2]), "r"(a[3]), "r"(b[0]), "r"(b[1]));
}
// load one 128x64 fp16 tile (row-major) into SW128-swizzled smem
__device__ __forceinline__ void load_tile_h(const __half* __restrict__ src, int ld,
                                            int k0, uint32_t dst, int tid) {
    #pragma unroll
    for (int i = 0; i < 4; ++i) {
        int idx = i * 256 + tid;
        int r = idx >> 3, f = idx & 7;
        cp_async16(dst + sw128((uint32_t)(r * 128 + f * 16)),
                   src + (size_t)r * ld + k0 + f * 8);
    }
}
// load one 64x64 fp16 tile
__device__ __forceinline__ void load_tile_h64(const __half* __restrict__ src, int ld,
                                              int k0, uint32_t dst, int tid) {
    #pragma unroll
    for (int i = 0; i < 2; ++i) {
        int idx = i * 256 + tid;
        int r = idx >> 3, f = idx & 7;
        cp_async16(dst + sw128((uint32_t)(r * 128 + f * 16)),
                   src + (size_t)r * ld + k0 + f * 8);
    }
}

// ================ FP16 HMMA GEMM, 128x128 CTA tile, 3-stage pipeline ================
// EPI: 0 fp16 out; 2 gelu -> fp16 out
#define HMM_SMEM_BYTES 98304
template <int EPI>
__global__ void __launch_bounds__(256) hmm_kernel(const __half* __restrict__ A,
                                                  const __half* __restrict__ Bt,
                                                  const float* __restrict__ bias,
                                                  void* __restrict__ Cout,
                                                  int M, int N, int K) {
    extern __shared__ char smem[];
    const int tid = threadIdx.x;
    const int wid = tid >> 5, lane = tid & 31;
    const int bx = blockIdx.x, by = blockIdx.y;
    const uint32_t sb = s2u(smem);
    uint32_t asb[3], bsb[3];
    #pragma unroll
    for (int s = 0; s < 3; ++s) { asb[s] = sb + s * 16384; bsb[s] = sb + 49152 + s * 16384; }

    const __half* Abase = A + (size_t)by * 128 * K;
    const __half* Bbase = Bt + (size_t)bx * 128 * K;
    const int nk = K >> 6;

    const int warp_m = (wid >> 2) * 64;
    const int warp_n = (wid & 3) * 32;

    float acc[4][4][4];
    #pragma unroll
    for (int i = 0; i < 4; ++i)
        #pragma unroll
        for (int j = 0; j < 4; ++j)
            #pragma unroll
            for (int q = 0; q < 4; ++q) acc[i][j][q] = 0.f;

    load_tile_h(Abase, K, 0, asb[0], tid);
    load_tile_h(Bbase, K, 0, bsb[0], tid);
    cp_commit();
    if (nk > 1) {
        load_tile_h(Abase, K, 64, asb[1], tid);
        load_tile_h(Bbase, K, 64, bsb[1], tid);
    }
    cp_commit();

    const int a_row = (lane & 7) + ((lane >> 3) & 1) * 8;
    const int a_kc  = (lane >> 4) * 8;
    const int b_nr  = (lane & 7) + ((lane >> 4) * 8);
    const int b_kc  = ((lane >> 3) & 1) * 8;

    for (int c = 0; c < nk; ++c) {
        if (c == nk - 1) cp_wait<0>(); else cp_wait<1>();
        __syncthreads();
        const int cur = c % 3;
        const uint32_t abuf = asb[cur];
        const uint32_t bbuf = bsb[cur];

        #pragma unroll
        for (int ks = 0; ks < 4; ++ks) {
            uint32_t a[4][4];
            #pragma unroll
            for (int mt = 0; mt < 4; ++mt) {
                int row = warp_m + mt * 16 + a_row;
                int kc = ks * 16 + a_kc;
                ldsm_x4(a[mt], abuf + sw128((uint32_t)(row * 128 + kc * 2)));
            }
            uint32_t b[4][2];
            #pragma unroll
            for (int np = 0; np < 2; ++np) {
                uint32_t r4[4];
                int nrow = warp_n + np * 16 + b_nr;
                int kc = ks * 16 + b_kc;
                ldsm_x4(r4, bbuf + sw128((uint32_t)(nrow * 128 + kc * 2)));
                b[np * 2 + 0][0] = r4[0]; b[np * 2 + 0][1] = r4[1];
                b[np * 2 + 1][0] = r4[2]; b[np * 2 + 1][1] = r4[3];
            }
            #pragma unroll
            for (int mt = 0; mt < 4; ++mt)
                #pragma unroll
                for (int nt = 0; nt < 4; ++nt)
                    mma_f16(acc[mt][nt], a[mt], b[nt]);
        }
        if (c + 2 < nk) {
            int ns = (c + 2) % 3;
            load_tile_h(Abase, K, (c + 2) * 64, asb[ns], tid);
            load_tile_h(Bbase, K, (c + 2) * 64, bsb[ns], tid);
        }
        cp_commit();
    }

    const int erow = lane >> 2;
    const int ecol = (lane & 3) * 2;
    #pragma unroll
    for (int nt = 0; nt < 4; ++nt) {
        int gcol = bx * 128 + warp_n + nt * 8 + ecol;
        float b0 = bias[gcol], b1 = bias[gcol + 1];
        #pragma unroll
        for (int mt = 0; mt < 4; ++mt) {
            #pragma unroll
            for (int h = 0; h < 2; ++h) {
                int grow = by * 128 + warp_m + mt * 16 + erow + h * 8;
                if (grow >= M) continue;
                float v0 = acc[mt][nt][h * 2 + 0] + b0;
                float v1 = acc[mt][nt][h * 2 + 1] + b1;
                if (EPI == 2) {
                    v0 = 0.5f * v0 * (1.f + erff(v0 * 0.70710678118654752f));
                    v1 = 0.5f * v1 * (1.f + erff(v1 * 0.70710678118654752f));
                }
                __half2 hp = __floats2half2_rn(v0, v1);
                *reinterpret_cast<__half2*>((__half*)Cout + (size_t)grow * N + gcol) = hp;
            }
        }
    }
}

// ================ FP16 HMMA GEMM, 128x64 CTA tile ================
// EPI: 1 scatter+residual fp32; 3 +R residual fp32
#define HMM64_SMEM_BYTES 73728
template <int EPI>
__global__ void __launch_bounds__(256) hmm64_kernel(const __half* __restrict__ A,
                                                    const __half* __restrict__ Bt,
                                                    const float* __restrict__ bias,
                                                    float* __restrict__ Cout,
                                                    const float* __restrict__ X,
                                                    int M, int N, int K) {
    extern __shared__ char smem[];
    const int tid = threadIdx.x;
    const int wid = tid >> 5, lane = tid & 31;
    const int bx = blockIdx.x, by = blockIdx.y;
    const uint32_t sb = s2u(smem);
    uint32_t asb[3], bsb[3];
    #pragma unroll
    for (int s = 0; s < 3; ++s) { asb[s] = sb + s * 16384; bsb[s] = sb + 49152 + s * 8192; }

    const __half* Abase = A + (size_t)by * 128 * K;
    const __half* Bbase = Bt + (size_t)bx * 64 * K;
    const int nk = K >> 6;

    const int warp_m = (wid >> 1) * 32;
    const int warp_n = (wid & 1) * 32;

    float acc[2][4][4];
    #pragma unroll
    for (int i = 0; i < 2; ++i)
        #pragma unroll
        for (int j = 0; j < 4; ++j)
            #pragma unroll
            for (int q = 0; q < 4; ++q) acc[i][j][q] = 0.f;

    load_tile_h(Abase, K, 0, asb[0], tid);
    load_tile_h64(Bbase, K, 0, bsb[0], tid);
    cp_commit();
    if (nk > 1) {
        load_tile_h(Abase, K, 64, asb[1], tid);
        load_tile_h64(Bbase, K, 64, bsb[1], tid);
    }
    cp_commit();

    const int a_row = (lane & 7) + ((lane >> 3) & 1) * 8;
    const int a_kc  = (lane >> 4) * 8;
    const int b_nr  = (lane & 7) + ((lane >> 4) * 8);
    const int b_kc  = ((lane >> 3) & 1) * 8;

    for (int c = 0; c < nk; ++c) {
        if (c == nk - 1) cp_wait<0>(); else cp_wait<1>();
        __syncthreads();
        const int cur = c % 3;
        const uint32_t abuf = asb[cur];
        const uint32_t bbuf = bsb[cur];

        #pragma unroll
        for (int ks = 0; ks < 4; ++ks) {
            uint32_t a[2][4];
            #pragma unroll
            for (int mt = 0; mt < 2; ++mt) {
                int row = warp_m + mt * 16 + a_row;
                int kc = ks * 16 + a_kc;
                ldsm_x4(a[mt], abuf + sw128((uint32_t)(row * 128 + kc * 2)));
            }
            uint32_t b[4][2];
            #pragma unroll
            for (int np = 0; np < 2; ++np) {
                uint32_t r4[4];
                int nrow = warp_n + np * 16 + b_nr;
                int kc = ks * 16 + b_kc;
                ldsm_x4(r4, bbuf + sw128((uint32_t)(nrow * 128 + kc * 2)));
                b[np * 2 + 0][0] = r4[0]; b[np * 2 + 0][1] = r4[1];
                b[np * 2 + 1][0] = r4[2]; b[np * 2 + 1][1] = r4[3];
            }
            #pragma unroll
            for (int mt = 0; mt < 2; ++mt)
                #pragma unroll
                for (int nt = 0; nt < 4; ++nt)
                    mma_f16(acc[mt][nt], a[mt], b[nt]);
        }
        if (c + 2 < nk) {
            int ns = (c + 2) % 3;
            load_tile_h(Abase, K, (c + 2) * 64, asb[ns], tid);
            load_tile_h64(Bbase, K, (c + 2) * 64, bsb[ns], tid);
        }
        cp_commit();
    }

    const int erow = lane >> 2;
    const int ecol = (lane & 3) * 2;
    #pragma unroll
    for (int nt = 0; nt < 4; ++nt) {
        int gcol = bx * 64 + warp_n + nt * 8 + ecol;
        float b0 = bias[gcol], b1 = bias[gcol + 1];
        #pragma unroll
        for (int mt = 0; mt < 2; ++mt) {
            #pragma unroll
            for (int h = 0; h < 2; ++h) {
                int grow = by * 128 + warp_m + mt * 16 + erow + h * 8;
                if (grow >= M) continue;
                float v0 = acc[mt][nt][h * 2 + 0] + b0;
                float v1 = acc[mt][nt][h * 2 + 1] + b1;
                if (EPI == 1) {
                    int win = grow / NTOK, t = grow % NTOK;
                    if (win < NWIN) {
                        int bb = win / 25, wrem = win % 25;
                        int r = (wrem / 5) * WS + t / WS;
                        int cc = (wrem % 5) * WS + t % WS;
                        if (r < HH && cc < WW_) {
                            size_t base = ((size_t)bb * L + r * WW_ + cc) * DIM + gcol;
                            float2 xv = *reinterpret_cast<const float2*>(X + base);
                            float2 o = make_float2(v0 + xv.x, v1 + xv.y);
                            *reinterpret_cast<float2*>(Cout + base) = o;
                        }
                    }
                } else {
                    float2 r2 = *reinterpret_cast<const float2*>(X + (size_t)grow * N + gcol);
                    float2 o = make_float2(v0 + r2.x, v1 + r2.y);
                    *reinterpret_cast<float2*>(Cout + (size_t)grow * N + gcol) = o;
                }
            }
        }
    }
}

// ---------------- fused prep ----------------
#define WQ_E (DIM * 3 * DIM)
#define WP_E (DIM * DIM)
#define W1_E (DIM * FFN)
#define W2_E (FFN * DIM)
#define BI_E (NH * NTOK * NTOK)
#define PREP_TOTAL (WQ_E + WP_E + W1_E + W2_E + BI_E)
__global__ void prep_kernel(const float* __restrict__ qkv_w,
                            const float* __restrict__ proj_w,
                            const float* __restrict__ fc1_w,
                            const float* __restrict__ fc2_w,
                            const float* __restrict__ attn_bias,
                            const int* __restrict__ bias_idxs) {
    int idx = blockIdx.x * 256 + threadIdx.x;
    if (idx < WQ_E) {
        int k = idx / (3 * DIM), n = idx % (3 * DIM);
        g_wqh[(size_t)n * DIM + k] = __float2half(qkv_w[idx]);
        return;
    }
    idx -= WQ_E;
    if (idx < WP_E) {
        int k = idx / DIM, n = idx % DIM;
        g_wph[(size_t)n * DIM + k] = __float2half(proj_w[idx]);
        return;
    }
    idx -= WP_E;
    if (idx < W1_E) {
        int k = idx / FFN, n = idx % FFN;
        g_w1h[(size_t)n * DIM + k] = __float2half(fc1_w[idx]);
        return;
    }
    idx -= W1_E;
    if (idx < W2_E) {
        int k = idx / DIM, n = idx % DIM;
        g_w2h[(size_t)n * FFN + k] = __float2half(fc2_w[idx]);
        return;
    }
    idx -= W2_E;
    if (idx < BI_E) {
        int h = idx / (NTOK * NTOK), i = idx % (NTOK * NTOK);
        g_biasf[idx] = attn_bias[h * NTOK + bias_idxs[i]];
    }
}

// ---------------- block reduce ----------------
__device__ __forceinline__ void blockReduce2_128(float& a, float& b) {
    __shared__ float sa[4], sb_[4];
    int lane = threadIdx.x & 31, wid = threadIdx.x >> 5;
    #pragma unroll
    for (int o = 16; o > 0; o >>= 1) {
        a += __shfl_down_sync(0xffffffffu, a, o);
        b += __shfl_down_sync(0xffffffffu, b, o);
    }
    if (lane == 0) { sa[wid] = a; sb_[wid] = b; }
    __syncthreads();
    if (threadIdx.x == 0) {
        a = sa[0] + sa[1] + sa[2] + sa[3];
        b = sb_[0] + sb_[1] + sb_[2] + sb_[3];
        sa[0] = a; sb_[0] = b;
    }
    __syncthreads();
    a = sa[0]; b = sb_[0];
    __syncthreads();
}

// ---------------- LN1 + window partition -> fp16 ----------------
__global__ void ln1_window_kernel(const float* __restrict__ x,
                                  const float* __restrict__ w,
                                  const float* __restrict__ b) {
    int g = blockIdx.x;
    int win = g / NTOK, t = g % NTOK;
    int bb = win / 25, wrem = win % 25;
    int wh = wrem / 5, wwi = wrem % 5;
    int i = t / WS, j = t % WS;
    int row = wh * WS + i, col = wwi * WS + j;
    bool valid = (row < HH) && (col < WW_);
    const float* xp = x + ((size_t)bb * L + row * WW_ + col) * DIM;
    int tid = threadIdx.x;
    float vals[3];
    float s = 0.f, sq = 0.f;
    #pragma unroll
    for (int c = 0; c < 3; ++c) {
        float v = valid ? xp[tid + c * 128] : 0.f;
        vals[c] = v; s += v; sq += v * v;
    }
    blockReduce2_128(s, sq);
    float mu = s * (1.f / DIM);
    float var = sq * (1.f / DIM) - mu * mu;
    float inv = rsqrtf(var + EPSV);
    __half* op = g_xn + (size_t)g * DIM;
    #pragma unroll
    for (int c = 0; c < 3; ++c) {
        int idx = tid + c * 128;
        op[idx] = __float2half((vals[c] - mu) * inv * w[idx] + b[idx]);
    }
}

// ---------------- fused conv3x3 + BN + LN2 ----------------
__global__ void conv_bn_ln2_kernel(const float* __restrict__ cw,
                                   const float* __restrict__ bg,
                                   const float* __restrict__ bb_,
                                   const float* __restrict__ bm,
                                   const float* __restrict__ bv,
                                   const float* __restrict__ lw,
                                   const float* __restrict__ lb) {
    int g = blockIdx.x;
    int l = g % L, bb = g / L;
    int row = l / WW_, col = l % WW_;
    int tid = threadIdx.x;

    float y[3];
    float s = 0.f, sq = 0.f;
    #pragma unroll
    for (int cc3 = 0; cc3 < 3; ++cc3) {
        int c = tid + cc3 * 128;
        float acc = 0.f;
        #pragma unroll
        for (int dh = -1; dh <= 1; ++dh) {
            #pragma unroll
            for (int dw = -1; dw <= 1; ++dw) {
                int r = row + dh, cl = col + dw;
                if (r >= 0 && r < HH && cl >= 0 && cl < WW_) {
                    acc += g_xa[((size_t)bb * L + r * WW_ + cl) * DIM + c] *
                           cw[c * 9 + (dh + 1) * 3 + (dw + 1)];
                }
            }
        }
        float inv = rsqrtf(bv[c] + EPSV);
        float v = (acc - bm[c]) * inv * bg[c] + bb_[c];
        y[cc3] = v;
        g_xb[(size_t)g * DIM + c] = v;
        s += v; sq += v * v;
    }
    blockReduce2_128(s, sq);
    float mu = s * (1.f / DIM);
    float var = sq * (1.f / DIM) - mu * mu;
    float inv2 = rsqrtf(var + EPSV);
    __half* op = g_xn2 + (size_t)g * DIM;
    #pragma unroll
    for (int cc3 = 0; cc3 < 3; ++cc3) {
        int c = tid + cc3 * 128;
        op[c] = __float2half((y[cc3] - mu) * inv2 * lw[c] + lb[c]);
    }
}

// ---------------- tensor-core windowed attention, 4 heads/block ----------------
// block = (window, head-quad), 512 threads = 16 warps = 4 groups of 4.
// Group wg handles head hq*4+wg; per-group smem: q[64x32] k[64x32] vt[32x72].
// Coalesced loads: heads hq*4..hq*4+3 span contiguous 768B per token row.
#define VT_STRIDE 72
#define AT_HEAD_BYTES 12800          // 4096 (q) + 4096 (k) + 4608 (vt)
#define AT_SMEM_BYTES (4 * AT_HEAD_BYTES)   // 51200
__global__ void __launch_bounds__(512) attn_kernel() {
    extern __shared__ char asmem[];
    const int w = blockIdx.x;
    const int hq = blockIdx.y;        // 0..2
    const int tid = threadIdx.x;
    const int wid = tid >> 5, lane = tid & 31;
    const int wg = wid >> 2;          // head within quad, 0..3
    const int wwid = wid & 3;         // warp within head group
    const int h = hq * 4 + wg;

    char* hb = asmem + wg * AT_HEAD_BYTES;
    const uint32_t qb = s2u(hb), kb = qb + 4096, vb = qb + 8192;

    // zero all 4 vt regions (0 * NaN safety for padded token cols of P@V)
    for (int i = tid; i < 4 * (4608 / 16); i += 512) {
        int hh = i / (4608 / 16), o = i % (4608 / 16);
        *reinterpret_cast<uint4*>(asmem + hh * AT_HEAD_BYTES + 8192 + o * 16) =
            make_uint4(0, 0, 0, 0);
    }

    // coalesced load of 4 heads' q/k/v: contiguous 384 halves per token
    const __half* base = g_qkv + (size_t)w * NTOK * (3 * DIM) + hq * 384;
    for (int idx = tid; idx < NTOK * 48; idx += 512) {
        int t = idx / 48, u = idx % 48;
        int col = u * 8;                  // 0..376, multiple of 8
        int hs = col / 96, cc = col % 96; // head-in-quad, offset within head
        int sec = cc >> 5, d = cc & 31;   // 0=q,1=k,2=v ; d multiple of 8
        uint4 v4 = *reinterpret_cast<const uint4*>(base + (size_t)t * (3 * DIM) + col);
        char* dst = asmem + hs * AT_HEAD_BYTES;
        if (sec == 0) {
            *reinterpret_cast<uint4*>(dst + (t * 32 + d) * 2) = v4;
        } else if (sec == 1) {
            *reinterpret_cast<uint4*>(dst + 4096 + (t * 32 + d) * 2) = v4;
        } else {
            __half h8[8];
            *reinterpret_cast<uint4*>(h8) = v4;
            __half* vtd = reinterpret_cast<__half*>(dst + 8192);
            #pragma unroll
            for (int j = 0; j < 8; ++j)
                vtd[(d + j) * VT_STRIDE + t] = h8[j];
        }
    }
    __syncthreads();

    const int a_row = (lane & 7) + ((lane >> 3) & 1) * 8;
    const int a_kc  = (lane >> 4) * 8;
    const int b_nr  = (lane & 7) + ((lane >> 4) * 8);
    const int b_kc  = ((lane >> 3) & 1) * 8;
    const int erow = lane >> 2;
    const int ecol = (lane & 3) * 2;
    const int wm = wwid * 16;

    // ---- S = Q @ K^T ----
    float acc[8][4];
    #pragma unroll
    for (int nt = 0; nt < 8; ++nt)
        #pragma unroll
        for (int qq = 0; qq < 4; ++qq) acc[nt][qq] = 0.f;

    #pragma unroll
    for (int ks = 0; ks < 2; ++ks) {
        uint32_t a[4];
        ldsm_x4(a, qb + (uint32_t)((wm + a_row) * 64 + (ks * 16 + a_kc) * 2));
        uint32_t b[8][2];
        #pragma unroll
        for (int np = 0; np < 4; ++np) {
            uint32_t r4[4];
            ldsm_x4(r4, kb + (uint32_t)((np * 16 + b_nr) * 64 + (ks * 16 + b_kc) * 2));
            b[np * 2 + 0][0] = r4[0]; b[np * 2 + 0][1] = r4[1];
            b[np * 2 + 1][0] = r4[2]; b[np * 2 + 1][1] = r4[3];
        }
        #pragma unroll
        for (int nt = 0; nt < 8; ++nt)
            mma_f16(acc[nt], a, b[nt]);
    }

    // ---- scale + bias + mask in registers ----
    const float scale = 0.1767766952966369f;
    const float* bf = g_biasf + (size_t)h * NTOK * NTOK;
    const int row0 = wm + erow, row1 = row0 + 8;
    const bool r0v = row0 < NTOK, r1v = row1 < NTOK;
    #pragma unroll
    for (int nt = 0; nt < 8; ++nt) {
        int col = nt * 8 + ecol;
        bool c0v = col < NTOK, c1v = (col + 1) < NTOK;
        acc[nt][0] = (r0v && c0v) ? acc[nt][0] * scale + bf[row0 * NTOK + col]     : -1e30f;
        acc[nt][1] = (r0v && c1v) ? acc[nt][1] * scale + bf[row0 * NTOK + col + 1] : -1e30f;
        acc[nt][2] = (r1v && c0v) ? acc[nt][2] * scale + bf[row1 * NTOK + col]     : -1e30f;
        acc[nt][3] = (r1v && c1v) ? acc[nt][3] * scale + bf[row1 * NTOK + col + 1] : -1e30f;
    }

    // ---- register softmax ----
    float m0 = -1e30f, m1 = -1e30f;
    #pragma unroll
    for (int nt = 0; nt < 8; ++nt) {
        m0 = fmaxf(m0, fmaxf(acc[nt][0], acc[nt][1]));
        m1 = fmaxf(m1, fmaxf(acc[nt][2], acc[nt][3]));
    }
    m0 = fmaxf(m0, __shfl_xor_sync(0xffffffffu, m0, 1));
    m0 = fmaxf(m0, __shfl_xor_sync(0xffffffffu, m0, 2));
    m1 = fmaxf(m1, __shfl_xor_sync(0xffffffffu, m1, 1));
    m1 = fmaxf(m1, __shfl_xor_sync(0xffffffffu, m1, 2));
    float s0 = 0.f, s1 = 0.f;
    #pragma unroll
    for (int nt = 0; nt < 8; ++nt) {
        acc[nt][0] = expf(acc[nt][0] - m0);
        acc[nt][1] = expf(acc[nt][1] - m0);
        acc[nt][2] = expf(acc[nt][2] - m1);
        acc[nt][3] = expf(acc[nt][3] - m1);
        s0 += acc[nt][0] + acc[nt][1];
        s1 += acc[nt][2] + acc[nt][3];
    }
    s0 += __shfl_xor_sync(0xffffffffu, s0, 1);
    s0 += __shfl_xor_sync(0xffffffffu, s0, 2);
    s1 += __shfl_xor_sync(0xffffffffu, s1, 1);
    s1 += __shfl_xor_sync(0xffffffffu, s1, 2);
    const float inv0 = 1.f / s0, inv1 = 1.f / s1;

    // ---- P A-fragments from normalized S C-fragments ----
    uint32_t pf[4][4];
    #pragma unroll
    for (int ks = 0; ks < 4; ++ks) {
        __half2 t0 = __floats2half2_rn(acc[2 * ks][0] * inv0, acc[2 * ks][1] * inv0);
        __half2 t1 = __floats2half2_rn(acc[2 * ks][2] * inv1, acc[2 * ks][3] * inv1);
        __half2 t2 = __floats2half2_rn(acc[2 * ks + 1][0] * inv0, acc[2 * ks + 1][1] * inv0);
        __half2 t3 = __floats2half2_rn(acc[2 * ks + 1][2] * inv1, acc[2 * ks + 1][3] * inv1);
        pf[ks][0] = *reinterpret_cast<uint32_t*>(&t0);
        pf[ks][1] = *reinterpret_cast<uint32_t*>(&t1);
        pf[ks][2] = *reinterpret_cast<uint32_t*>(&t2);
        pf[ks][3] = *reinterpret_cast<uint32_t*>(&t3);
    }

    // ---- O = P @ V ----
    float oacc[4][4];
    #pragma unroll
    for (int nt = 0; nt < 4; ++nt)
        #pragma unroll
        for (int qq = 0; qq < 4; ++qq) oacc[nt][qq] = 0.f;

    #pragma unroll
    for (int ks = 0; ks < 4; ++ks) {
        uint32_t b[4][2];
        #pragma unroll
        for (int np = 0; np < 2; ++np) {
            uint32_t r4[4];
            ldsm_x4(r4, vb + (uint32_t)((np * 16 + b_nr) * (VT_STRIDE * 2) + (ks * 16 + b_kc) * 2));
            b[np * 2 + 0][0] = r4[0]; b[np * 2 + 0][1] = r4[1];
            b[np * 2 + 1][0] = r4[2]; b[np * 2 + 1][1] = r4[3];
        }
        #pragma unroll
        for (int nt = 0; nt < 4; ++nt)
            mma_f16(oacc[nt], pf[ks], b[nt]);
    }

    #pragma unroll
    for (int nt = 0; nt < 4; ++nt) {
        #pragma unroll
        for (int hh = 0; hh < 2; ++hh) {
            int row = wm + erow + hh * 8;
            if (row >= NTOK) continue;
            int col = nt * 8 + ecol;
            __half2 hp = __floats2half2_rn(oacc[nt][hh * 2 + 0], oacc[nt][hh * 2 + 1]);
            *reinterpret_cast<__half2*>(
                g_ao + ((size_t)w * NTOK + row) * DIM + h * HD + col) = hp;
        }
    }
}

// ---------------- launch ----------------
extern "C" void kernel_launch(void* const* d_in, const int* in_sizes, int n_in,
                              void* d_out, int out_size) {
    const float* x         = (const float*)d_in[0];
    const float* ln1_w     = (const float*)d_in[1];
    const float* ln1_b     = (const float*)d_in[2];
    const float* qkv_w     = (const float*)d_in[3];
    const float* qkv_b     = (const float*)d_in[4];
    const float* proj_w    = (const float*)d_in[5];
    const float* proj_b    = (const float*)d_in[6];
    const float* attn_bias = (const float*)d_in[7];
    const int*   bias_idxs = (const int*)d_in[8];
    const float* conv_w    = (const float*)d_in[9];
    const float* bn_g      = (const float*)d_in[10];
    const float* bn_b      = (const float*)d_in[11];
    const float* bn_m      = (const float*)d_in[12];
    const float* bn_v      = (const float*)d_in[13];
    const float* ln2_w     = (const float*)d_in[14];
    const float* ln2_b     = (const float*)d_in[15];
    const float* fc1_w     = (const float*)d_in[16];
    const float* fc1_b     = (const float*)d_in[17];
    const float* fc2_w     = (const float*)d_in[18];
    const float* fc2_b     = (const float*)d_in[19];
    float* out = (float*)d_out;

    __half *xn, *qkv, *ao, *xn2, *hbuf, *wqh, *wph, *w1h, *w2h;
    float *xa, *xb;
    cudaGetSymbolAddress((void**)&xn,  g_xn);
    cudaGetSymbolAddress((void**)&qkv, g_qkv);
    cudaGetSymbolAddress((void**)&ao,  g_ao);
    cudaGetSymbolAddress((void**)&xa,  g_xa);
    cudaGetSymbolAddress((void**)&xb,  g_xb);
    cudaGetSymbolAddress((void**)&xn2, g_xn2);
    cudaGetSymbolAddress((void**)&hbuf, g_h);
    cudaGetSymbolAddress((void**)&wqh, g_wqh);
    cudaGetSymbolAddress((void**)&wph, g_wph);
    cudaGetSymbolAddress((void**)&w1h, g_w1h);
    cudaGetSymbolAddress((void**)&w2h, g_w2h);

    cudaFuncSetAttribute(hmm_kernel<0>, cudaFuncAttributeMaxDynamicSharedMemorySize, HMM_SMEM_BYTES);
    cudaFuncSetAttribute(hmm_kernel<2>, cudaFuncAttributeMaxDynamicSharedMemorySize, HMM_SMEM_BYTES);
    cudaFuncSetAttribute(hmm64_kernel<1>, cudaFuncAttributeMaxDynamicSharedMemorySize, HMM64_SMEM_BYTES);
    cudaFuncSetAttribute(hmm64_kernel<3>, cudaFuncAttributeMaxDynamicSharedMemorySize, HMM64_SMEM_BYTES);
    cudaFuncSetAttribute(attn_kernel, cudaFuncAttributeMaxDynamicSharedMemorySize, AT_SMEM_BYTES);

    // 0) fused prep
    prep_kernel<<<(PREP_TOTAL + 255) / 256, 256>>>(qkv_w, proj_w, fc1_w, fc2_w,
                                                   attn_bias, bias_idxs);

    // 1) LN1 + window partition (fp16)
    ln1_window_kernel<<<TOKENS, 128>>>(x, ln1_w, ln1_b);

    // 2) qkv GEMM (fp16, 128x128)
    {
        dim3 grid((3 * DIM) / 128, MPAD / 128);
        hmm_kernel<0><<<grid, 256, HMM_SMEM_BYTES>>>(xn, wqh, qkv_b, qkv,
                                                     TOKENS, 3 * DIM, DIM);
    }

    // 3) windowed attention (4 heads/block, coalesced loads)
    {
        dim3 grid(NWIN, NH / 4);
        attn_kernel<<<grid, 512, AT_SMEM_BYTES>>>();
    }

    // 4) proj GEMM (fp16, 128x64) + fused scatter/residual -> g_xa
    {
        dim3 grid(DIM / 64, MPAD / 128);
        hmm64_kernel<1><<<grid, 256, HMM64_SMEM_BYTES>>>(ao, wph, proj_b, xa, x,
                                                         TOKENS, DIM, DIM);
    }

    // 5) conv + BN + LN2 (fused)
    conv_bn_ln2_kernel<<<BL, 128>>>(conv_w, bn_g, bn_b, bn_m, bn_v, ln2_w, ln2_b);

    // 6) fc1 + gelu (fp16, 128x128)
    {
        dim3 grid(FFN / 128, BL / 128);
        hmm_kernel<2><<<grid, 256, HMM_SMEM_BYTES>>>(xn2, w1h, fc1_b, hbuf,
                                                     BL, FFN, DIM);
    }

    // 7) fc2 + residual -> out (fp16, 128x64)
    {
        dim3 grid(DIM / 64, BL / 128);
        hmm64_kernel<3><<<grid, 256, HMM64_SMEM_BYTES>>>(hbuf, w2h, fc2_b, out, xb,
                                                         BL, DIM, FFN);
    }
}

// round 17
// speedup vs baseline: 1.0664x; 1.0664x over previous
#include <cuda_runtime.h>
#include <cuda_fp16.h>
#include <math.h>
#include <stdint.h>

#define BATCH 32
#define HH 32
#define WW_ 32
#define L 1024
#define DIM 384
#define NH 12
#define HD 32
#define WS 7
#define NWIN 800
#define NTOK 49
#define TOKENS (NWIN * NTOK)   // 39200
#define MPAD 39296
#define BL (BATCH * L)         // 32768
#define FFN (4 * DIM)          // 1536
#define EPSV 1e-5f

// ---------------- scratch ----------------
__device__ __half g_xn[(size_t)MPAD * DIM];
__device__ __half g_qkv[(size_t)MPAD * 3 * DIM];
__device__ __half g_ao[(size_t)MPAD * DIM];
__device__ float  g_xa[(size_t)BL * DIM];
__device__ float  g_xb[(size_t)BL * DIM];
__device__ __half g_xn2[(size_t)BL * DIM];
__device__ __half g_h[(size_t)BL * FFN];
__device__ __half g_wqh[(size_t)3 * DIM * DIM];
__device__ __half g_wph[(size_t)DIM * DIM];
__device__ __half g_w1h[(size_t)FFN * DIM];
__device__ __half g_w2h[(size_t)DIM * FFN];
__device__ float  g_biasf[(size_t)NH * NTOK * NTOK];

// ================= common helpers =================
__device__ __forceinline__ uint32_t s2u(const void* p) {
    uint32_t a;
    asm("{ .reg .u64 t; cvta.to.shared.u64 t, %1; cvt.u32.u64 %0, t; }" : "=r"(a) : "l"(p));
    return a;
}
__device__ __forceinline__ void cp_async16(uint32_t dst, const void* src) {
    asm volatile("cp.async.cg.shared.global [%0], [%1], 16;" :: "r"(dst), "l"(src) : "memory");
}
__device__ __forceinline__ void cp_commit() {
    asm volatile("cp.async.commit_group;" ::: "memory");
}
template <int N>
__device__ __forceinline__ void cp_wait() {
    asm volatile("cp.async.wait_group %0;" :: "n"(N) : "memory");
}
__device__ __forceinline__ uint32_t sw128(uint32_t byte_off) {
    return byte_off ^ ((byte_off >> 3) & 0x70u);
}
__device__ __forceinline__ void ldsm_x4(uint32_t* r, uint32_t addr) {
    asm volatile("ldmatrix.sync.aligned.m8n8.x4.shared.b16 {%0,%1,%2,%3}, [%4];"
                 : "=r"(r[0]), "=r"(r[1]), "=r"(r[2]), "=r"(r[3]) : "r"(addr));
}
__device__ __forceinline__ void mma_f16(float* c, const uint32_t* a, const uint32_t* b) {
    asm volatile("mma.sync.aligned.m16n8k16.row.col.f32.f16.f16.f32 "
                 "{%0,%1,%2,%3}, {%4,%5,%6,%7}, {%8,%9}, {%0,%1,%2,%3};"
                 : "+f"(c[0]), "+f"(c[1]), "+f"(c[2]), "+f"(c[3])
                 : "r"(a[0]), "r"(a[1]), "r"(a[2]), "r"(a[3]), "r"(b[0]), "r"(b[1]));
}
// load one 128x64 fp16 tile (row-major) into SW128-swizzled smem
__device__ __forceinline__ void load_tile_h(const __half* __restrict__ src, int ld,
                                            int k0, uint32_t dst, int tid) {
    #pragma unroll
    for (int i = 0; i < 4; ++i) {
        int idx = i * 256 + tid;
        int r = idx >> 3, f = idx & 7;
        cp_async16(dst + sw128((uint32_t)(r * 128 + f * 16)),
                   src + (size_t)r * ld + k0 + f * 8);
    }
}
// load one 64x64 fp16 tile
__device__ __forceinline__ void load_tile_h64(const __half* __restrict__ src, int ld,
                                              int k0, uint32_t dst, int tid) {
    #pragma unroll
    for (int i = 0; i < 2; ++i) {
        int idx = i * 256 + tid;
        int r = idx >> 3, f = idx & 7;
        cp_async16(dst + sw128((uint32_t)(r * 128 + f * 16)),
                   src + (size_t)r * ld + k0 + f * 8);
    }
}

// ================ FP16 HMMA GEMM, 128x128 CTA tile, 3-stage pipeline ================
// EPI: 0 fp16 out; 2 gelu -> fp16 out
#define HMM_SMEM_BYTES 98304
template <int EPI>
__global__ void __launch_bounds__(256) hmm_kernel(const __half* __restrict__ A,
                                                  const __half* __restrict__ Bt,
                                                  const float* __restrict__ bias,
                                                  void* __restrict__ Cout,
                                                  int M, int N, int K) {
    extern __shared__ char smem[];
    const int tid = threadIdx.x;
    const int wid = tid >> 5, lane = tid & 31;
    const int bx = blockIdx.x, by = blockIdx.y;
    const uint32_t sb = s2u(smem);
    uint32_t asb[3], bsb[3];
    #pragma unroll
    for (int s = 0; s < 3; ++s) { asb[s] = sb + s * 16384; bsb[s] = sb + 49152 + s * 16384; }

    const __half* Abase = A + (size_t)by * 128 * K;
    const __half* Bbase = Bt + (size_t)bx * 128 * K;
    const int nk = K >> 6;

    const int warp_m = (wid >> 2) * 64;
    const int warp_n = (wid & 3) * 32;

    float acc[4][4][4];
    #pragma unroll
    for (int i = 0; i < 4; ++i)
        #pragma unroll
        for (int j = 0; j < 4; ++j)
            #pragma unroll
            for (int q = 0; q < 4; ++q) acc[i][j][q] = 0.f;

    load_tile_h(Abase, K, 0, asb[0], tid);
    load_tile_h(Bbase, K, 0, bsb[0], tid);
    cp_commit();
    if (nk > 1) {
        load_tile_h(Abase, K, 64, asb[1], tid);
        load_tile_h(Bbase, K, 64, bsb[1], tid);
    }
    cp_commit();

    const int a_row = (lane & 7) + ((lane >> 3) & 1) * 8;
    const int a_kc  = (lane >> 4) * 8;
    const int b_nr  = (lane & 7) + ((lane >> 4) * 8);
    const int b_kc  = ((lane >> 3) & 1) * 8;

    for (int c = 0; c < nk; ++c) {
        if (c == nk - 1) cp_wait<0>(); else cp_wait<1>();
        __syncthreads();
        const int cur = c % 3;
        const uint32_t abuf = asb[cur];
        const uint32_t bbuf = bsb[cur];

        #pragma unroll
        for (int ks = 0; ks < 4; ++ks) {
            uint32_t a[4][4];
            #pragma unroll
            for (int mt = 0; mt < 4; ++mt) {
                int row = warp_m + mt * 16 + a_row;
                int kc = ks * 16 + a_kc;
                ldsm_x4(a[mt], abuf + sw128((uint32_t)(row * 128 + kc * 2)));
            }
            uint32_t b[4][2];
            #pragma unroll
            for (int np = 0; np < 2; ++np) {
                uint32_t r4[4];
                int nrow = warp_n + np * 16 + b_nr;
                int kc = ks * 16 + b_kc;
                ldsm_x4(r4, bbuf + sw128((uint32_t)(nrow * 128 + kc * 2)));
                b[np * 2 + 0][0] = r4[0]; b[np * 2 + 0][1] = r4[1];
                b[np * 2 + 1][0] = r4[2]; b[np * 2 + 1][1] = r4[3];
            }
            #pragma unroll
            for (int mt = 0; mt < 4; ++mt)
                #pragma unroll
                for (int nt = 0; nt < 4; ++nt)
                    mma_f16(acc[mt][nt], a[mt], b[nt]);
        }
        if (c + 2 < nk) {
            int ns = (c + 2) % 3;
            load_tile_h(Abase, K, (c + 2) * 64, asb[ns], tid);
            load_tile_h(Bbase, K, (c + 2) * 64, bsb[ns], tid);
        }
        cp_commit();
    }

    const int erow = lane >> 2;
    const int ecol = (lane & 3) * 2;
    #pragma unroll
    for (int nt = 0; nt < 4; ++nt) {
        int gcol = bx * 128 + warp_n + nt * 8 + ecol;
        float b0 = bias[gcol], b1 = bias[gcol + 1];
        #pragma unroll
        for (int mt = 0; mt < 4; ++mt) {
            #pragma unroll
            for (int h = 0; h < 2; ++h) {
                int grow = by * 128 + warp_m + mt * 16 + erow + h * 8;
                if (grow >= M) continue;
                float v0 = acc[mt][nt][h * 2 + 0] + b0;
                float v1 = acc[mt][nt][h * 2 + 1] + b1;
                if (EPI == 2) {
                    v0 = 0.5f * v0 * (1.f + erff(v0 * 0.70710678118654752f));
                    v1 = 0.5f * v1 * (1.f + erff(v1 * 0.70710678118654752f));
                }
                __half2 hp = __floats2half2_rn(v0, v1);
                *reinterpret_cast<__half2*>((__half*)Cout + (size_t)grow * N + gcol) = hp;
            }
        }
    }
}

// ================ FP16 HMMA GEMM, 128x64 CTA tile ================
// EPI: 1 scatter+residual fp32; 3 +R residual fp32
#define HMM64_SMEM_BYTES 73728
template <int EPI>
__global__ void __launch_bounds__(256) hmm64_kernel(const __half* __restrict__ A,
                                                    const __half* __restrict__ Bt,
                                                    const float* __restrict__ bias,
                                                    float* __restrict__ Cout,
                                                    const float* __restrict__ X,
                                                    int M, int N, int K) {
    extern __shared__ char smem[];
    const int tid = threadIdx.x;
    const int wid = tid >> 5, lane = tid & 31;
    const int bx = blockIdx.x, by = blockIdx.y;
    const uint32_t sb = s2u(smem);
    uint32_t asb[3], bsb[3];
    #pragma unroll
    for (int s = 0; s < 3; ++s) { asb[s] = sb + s * 16384; bsb[s] = sb + 49152 + s * 8192; }

    const __half* Abase = A + (size_t)by * 128 * K;
    const __half* Bbase = Bt + (size_t)bx * 64 * K;
    const int nk = K >> 6;

    const int warp_m = (wid >> 1) * 32;
    const int warp_n = (wid & 1) * 32;

    float acc[2][4][4];
    #pragma unroll
    for (int i = 0; i < 2; ++i)
        #pragma unroll
        for (int j = 0; j < 4; ++j)
            #pragma unroll
            for (int q = 0; q < 4; ++q) acc[i][j][q] = 0.f;

    load_tile_h(Abase, K, 0, asb[0], tid);
    load_tile_h64(Bbase, K, 0, bsb[0], tid);
    cp_commit();
    if (nk > 1) {
        load_tile_h(Abase, K, 64, asb[1], tid);
        load_tile_h64(Bbase, K, 64, bsb[1], tid);
    }
    cp_commit();

    const int a_row = (lane & 7) + ((lane >> 3) & 1) * 8;
    const int a_kc  = (lane >> 4) * 8;
    const int b_nr  = (lane & 7) + ((lane >> 4) * 8);
    const int b_kc  = ((lane >> 3) & 1) * 8;

    for (int c = 0; c < nk; ++c) {
        if (c == nk - 1) cp_wait<0>(); else cp_wait<1>();
        __syncthreads();
        const int cur = c % 3;
        const uint32_t abuf = asb[cur];
        const uint32_t bbuf = bsb[cur];

        #pragma unroll
        for (int ks = 0; ks < 4; ++ks) {
            uint32_t a[2][4];
            #pragma unroll
            for (int mt = 0; mt < 2; ++mt) {
                int row = warp_m + mt * 16 + a_row;
                int kc = ks * 16 + a_kc;
                ldsm_x4(a[mt], abuf + sw128((uint32_t)(row * 128 + kc * 2)));
            }
            uint32_t b[4][2];
            #pragma unroll
            for (int np = 0; np < 2; ++np) {
                uint32_t r4[4];
                int nrow = warp_n + np * 16 + b_nr;
                int kc = ks * 16 + b_kc;
                ldsm_x4(r4, bbuf + sw128((uint32_t)(nrow * 128 + kc * 2)));
                b[np * 2 + 0][0] = r4[0]; b[np * 2 + 0][1] = r4[1];
                b[np * 2 + 1][0] = r4[2]; b[np * 2 + 1][1] = r4[3];
            }
            #pragma unroll
            for (int mt = 0; mt < 2; ++mt)
                #pragma unroll
                for (int nt = 0; nt < 4; ++nt)
                    mma_f16(acc[mt][nt], a[mt], b[nt]);
        }
        if (c + 2 < nk) {
            int ns = (c + 2) % 3;
            load_tile_h(Abase, K, (c + 2) * 64, asb[ns], tid);
            load_tile_h64(Bbase, K, (c + 2) * 64, bsb[ns], tid);
        }
        cp_commit();
    }

    const int erow = lane >> 2;
    const int ecol = (lane & 3) * 2;
    #pragma unroll
    for (int nt = 0; nt < 4; ++nt) {
        int gcol = bx * 64 + warp_n + nt * 8 + ecol;
        float b0 = bias[gcol], b1 = bias[gcol + 1];
        #pragma unroll
        for (int mt = 0; mt < 2; ++mt) {
            #pragma unroll
            for (int h = 0; h < 2; ++h) {
                int grow = by * 128 + warp_m + mt * 16 + erow + h * 8;
                if (grow >= M) continue;
                float v0 = acc[mt][nt][h * 2 + 0] + b0;
                float v1 = acc[mt][nt][h * 2 + 1] + b1;
                if (EPI == 1) {
                    int win = grow / NTOK, t = grow % NTOK;
                    if (win < NWIN) {
                        int bb = win / 25, wrem = win % 25;
                        int r = (wrem / 5) * WS + t / WS;
                        int cc = (wrem % 5) * WS + t % WS;
                        if (r < HH && cc < WW_) {
                            size_t base = ((size_t)bb * L + r * WW_ + cc) * DIM + gcol;
                            float2 xv = *reinterpret_cast<const float2*>(X + base);
                            float2 o = make_float2(v0 + xv.x, v1 + xv.y);
                            *reinterpret_cast<float2*>(Cout + base) = o;
                        }
                    }
                } else {
                    float2 r2 = *reinterpret_cast<const float2*>(X + (size_t)grow * N + gcol);
                    float2 o = make_float2(v0 + r2.x, v1 + r2.y);
                    *reinterpret_cast<float2*>(Cout + (size_t)grow * N + gcol) = o;
                }
            }
        }
    }
}

// ---------------- fused prep ----------------
#define WQ_E (DIM * 3 * DIM)
#define WP_E (DIM * DIM)
#define W1_E (DIM * FFN)
#define W2_E (FFN * DIM)
#define BI_E (NH * NTOK * NTOK)
#define PREP_TOTAL (WQ_E + WP_E + W1_E + W2_E + BI_E)
__global__ void prep_kernel(const float* __restrict__ qkv_w,
                            const float* __restrict__ proj_w,
                            const float* __restrict__ fc1_w,
                            const float* __restrict__ fc2_w,
                            const float* __restrict__ attn_bias,
                            const int* __restrict__ bias_idxs) {
    int idx = blockIdx.x * 256 + threadIdx.x;
    if (idx < WQ_E) {
        int k = idx / (3 * DIM), n = idx % (3 * DIM);
        g_wqh[(size_t)n * DIM + k] = __float2half(qkv_w[idx]);
        return;
    }
    idx -= WQ_E;
    if (idx < WP_E) {
        int k = idx / DIM, n = idx % DIM;
        g_wph[(size_t)n * DIM + k] = __float2half(proj_w[idx]);
        return;
    }
    idx -= WP_E;
    if (idx < W1_E) {
        int k = idx / FFN, n = idx % FFN;
        g_w1h[(size_t)n * DIM + k] = __float2half(fc1_w[idx]);
        return;
    }
    idx -= W1_E;
    if (idx < W2_E) {
        int k = idx / DIM, n = idx % DIM;
        g_w2h[(size_t)n * FFN + k] = __float2half(fc2_w[idx]);
        return;
    }
    idx -= W2_E;
    if (idx < BI_E) {
        int h = idx / (NTOK * NTOK), i = idx % (NTOK * NTOK);
        g_biasf[idx] = attn_bias[h * NTOK + bias_idxs[i]];
    }
}

// ---------------- block reduce ----------------
__device__ __forceinline__ void blockReduce2_128(float& a, float& b) {
    __shared__ float sa[4], sb_[4];
    int lane = threadIdx.x & 31, wid = threadIdx.x >> 5;
    #pragma unroll
    for (int o = 16; o > 0; o >>= 1) {
        a += __shfl_down_sync(0xffffffffu, a, o);
        b += __shfl_down_sync(0xffffffffu, b, o);
    }
    if (lane == 0) { sa[wid] = a; sb_[wid] = b; }
    __syncthreads();
    if (threadIdx.x == 0) {
        a = sa[0] + sa[1] + sa[2] + sa[3];
        b = sb_[0] + sb_[1] + sb_[2] + sb_[3];
        sa[0] = a; sb_[0] = b;
    }
    __syncthreads();
    a = sa[0]; b = sb_[0];
    __syncthreads();
}

// ---------------- LN1 + window partition -> fp16 ----------------
__global__ void ln1_window_kernel(const float* __restrict__ x,
                                  const float* __restrict__ w,
                                  const float* __restrict__ b) {
    int g = blockIdx.x;
    int win = g / NTOK, t = g % NTOK;
    int bb = win / 25, wrem = win % 25;
    int wh = wrem / 5, wwi = wrem % 5;
    int i = t / WS, j = t % WS;
    int row = wh * WS + i, col = wwi * WS + j;
    bool valid = (row < HH) && (col < WW_);
    const float* xp = x + ((size_t)bb * L + row * WW_ + col) * DIM;
    int tid = threadIdx.x;
    float vals[3];
    float s = 0.f, sq = 0.f;
    #pragma unroll
    for (int c = 0; c < 3; ++c) {
        float v = valid ? xp[tid + c * 128] : 0.f;
        vals[c] = v; s += v; sq += v * v;
    }
    blockReduce2_128(s, sq);
    float mu = s * (1.f / DIM);
    float var = sq * (1.f / DIM) - mu * mu;
    float inv = rsqrtf(var + EPSV);
    __half* op = g_xn + (size_t)g * DIM;
    #pragma unroll
    for (int c = 0; c < 3; ++c) {
        int idx = tid + c * 128;
        op[idx] = __float2half((vals[c] - mu) * inv * w[idx] + b[idx]);
    }
}

// ---------------- fused conv3x3 + BN + LN2 ----------------
__global__ void conv_bn_ln2_kernel(const float* __restrict__ cw,
                                   const float* __restrict__ bg,
                                   const float* __restrict__ bb_,
                                   const float* __restrict__ bm,
                                   const float* __restrict__ bv,
                                   const float* __restrict__ lw,
                                   const float* __restrict__ lb) {
    int g = blockIdx.x;
    int l = g % L, bb = g / L;
    int row = l / WW_, col = l % WW_;
    int tid = threadIdx.x;

    float y[3];
    float s = 0.f, sq = 0.f;
    #pragma unroll
    for (int cc3 = 0; cc3 < 3; ++cc3) {
        int c = tid + cc3 * 128;
        float acc = 0.f;
        #pragma unroll
        for (int dh = -1; dh <= 1; ++dh) {
            #pragma unroll
            for (int dw = -1; dw <= 1; ++dw) {
                int r = row + dh, cl = col + dw;
                if (r >= 0 && r < HH && cl >= 0 && cl < WW_) {
                    acc += g_xa[((size_t)bb * L + r * WW_ + cl) * DIM + c] *
                           cw[c * 9 + (dh + 1) * 3 + (dw + 1)];
                }
            }
        }
        float inv = rsqrtf(bv[c] + EPSV);
        float v = (acc - bm[c]) * inv * bg[c] + bb_[c];
        y[cc3] = v;
        g_xb[(size_t)g * DIM + c] = v;
        s += v; sq += v * v;
    }
    blockReduce2_128(s, sq);
    float mu = s * (1.f / DIM);
    float var = sq * (1.f / DIM) - mu * mu;
    float inv2 = rsqrtf(var + EPSV);
    __half* op = g_xn2 + (size_t)g * DIM;
    #pragma unroll
    for (int cc3 = 0; cc3 < 3; ++cc3) {
        int c = tid + cc3 * 128;
        op[c] = __float2half((y[cc3] - mu) * inv2 * lw[c] + lb[c]);
    }
}

// ---------------- tensor-core windowed attention, register softmax ----------------
#define VT_STRIDE 72
__global__ void __launch_bounds__(128) attn_kernel() {
    __shared__ __half q[64 * 32];
    __shared__ __half k[64 * 32];
    __shared__ __half vt[32 * VT_STRIDE];

    const int w = blockIdx.x;
    const int h = blockIdx.y;
    const int tid = threadIdx.x;
    const int wid = tid >> 5, lane = tid & 31;
    const uint32_t qb = s2u(q), kb = s2u(k), vb = s2u(vt);

    // zero ONLY padded token cols of vt (t in [49,64), the range P@V reads).
    // Disjoint from the loader's t<49 writes -> no race, no extra sync.
    for (int i = tid; i < 32 * (64 - NTOK); i += 128) {
        int d = i / (64 - NTOK), t = NTOK + i % (64 - NTOK);
        vt[d * VT_STRIDE + t] = __float2half(0.f);
    }

    const __half* base = g_qkv + (size_t)w * NTOK * (3 * DIM);
    for (int i = tid; i < NTOK * 16; i += 128) {
        int t = i / 16, d2 = i % 16;
        const __half2* pp = reinterpret_cast<const __half2*>(
            base + (size_t)t * (3 * DIM) + h * 96) + d2;
        __half2 q2 = pp[0], k2 = pp[16], v2 = pp[32];
        *reinterpret_cast<__half2*>(q + t * 32 + d2 * 2) = q2;
        *reinterpret_cast<__half2*>(k + t * 32 + d2 * 2) = k2;
        vt[(d2 * 2 + 0) * VT_STRIDE + t] = __low2half(v2);
        vt[(d2 * 2 + 1) * VT_STRIDE + t] = __high2half(v2);
    }
    __syncthreads();

    const int a_row = (lane & 7) + ((lane >> 3) & 1) * 8;
    const int a_kc  = (lane >> 4) * 8;
    const int b_nr  = (lane & 7) + ((lane >> 4) * 8);
    const int b_kc  = ((lane >> 3) & 1) * 8;
    const int erow = lane >> 2;
    const int ecol = (lane & 3) * 2;
    const int wm = wid * 16;

    // ---- S = Q @ K^T ----
    float acc[8][4];
    #pragma unroll
    for (int nt = 0; nt < 8; ++nt)
        #pragma unroll
        for (int qq = 0; qq < 4; ++qq) acc[nt][qq] = 0.f;

    #pragma unroll
    for (int ks = 0; ks < 2; ++ks) {
        uint32_t a[4];
        ldsm_x4(a, qb + (uint32_t)((wm + a_row) * 64 + (ks * 16 + a_kc) * 2));
        uint32_t b[8][2];
        #pragma unroll
        for (int np = 0; np < 4; ++np) {
            uint32_t r4[4];
            ldsm_x4(r4, kb + (uint32_t)((np * 16 + b_nr) * 64 + (ks * 16 + b_kc) * 2));
            b[np * 2 + 0][0] = r4[0]; b[np * 2 + 0][1] = r4[1];
            b[np * 2 + 1][0] = r4[2]; b[np * 2 + 1][1] = r4[3];
        }
        #pragma unroll
        for (int nt = 0; nt < 8; ++nt)
            mma_f16(acc[nt], a, b[nt]);
    }

    // ---- scale + bias + mask in registers ----
    const float scale = 0.1767766952966369f;
    const float* bf = g_biasf + (size_t)h * NTOK * NTOK;
    const int row0 = wm + erow, row1 = row0 + 8;
    const bool r0v = row0 < NTOK, r1v = row1 < NTOK;
    #pragma unroll
    for (int nt = 0; nt < 8; ++nt) {
        int col = nt * 8 + ecol;
        bool c0v = col < NTOK, c1v = (col + 1) < NTOK;
        acc[nt][0] = (r0v && c0v) ? acc[nt][0] * scale + bf[row0 * NTOK + col]     : -1e30f;
        acc[nt][1] = (r0v && c1v) ? acc[nt][1] * scale + bf[row0 * NTOK + col + 1] : -1e30f;
        acc[nt][2] = (r1v && c0v) ? acc[nt][2] * scale + bf[row1 * NTOK + col]     : -1e30f;
        acc[nt][3] = (r1v && c1v) ? acc[nt][3] * scale + bf[row1 * NTOK + col + 1] : -1e30f;
    }

    // ---- register softmax ----
    float m0 = -1e30f, m1 = -1e30f;
    #pragma unroll
    for (int nt = 0; nt < 8; ++nt) {
        m0 = fmaxf(m0, fmaxf(acc[nt][0], acc[nt][1]));
        m1 = fmaxf(m1, fmaxf(acc[nt][2], acc[nt][3]));
    }
    m0 = fmaxf(m0, __shfl_xor_sync(0xffffffffu, m0, 1));
    m0 = fmaxf(m0, __shfl_xor_sync(0xffffffffu, m0, 2));
    m1 = fmaxf(m1, __shfl_xor_sync(0xffffffffu, m1, 1));
    m1 = fmaxf(m1, __shfl_xor_sync(0xffffffffu, m1, 2));
    float s0 = 0.f, s1 = 0.f;
    #pragma unroll
    for (int nt = 0; nt < 8; ++nt) {
        acc[nt][0] = __expf(acc[nt][0] - m0);
        acc[nt][1] = __expf(acc[nt][1] - m0);
        acc[nt][2] = __expf(acc[nt][2] - m1);
        acc[nt][3] = __expf(acc[nt][3] - m1);
        s0 += acc[nt][0] + acc[nt][1];
        s1 += acc[nt][2] + acc[nt][3];
    }
    s0 += __shfl_xor_sync(0xffffffffu, s0, 1);
    s0 += __shfl_xor_sync(0xffffffffu, s0, 2);
    s1 += __shfl_xor_sync(0xffffffffu, s1, 1);
    s1 += __shfl_xor_sync(0xffffffffu, s1, 2);
    const float inv0 = 1.f / s0, inv1 = 1.f / s1;

    // ---- P A-fragments from normalized S C-fragments ----
    uint32_t pf[4][4];
    #pragma unroll
    for (int ks = 0; ks < 4; ++ks) {
        __half2 t0 = __floats2half2_rn(acc[2 * ks][0] * inv0, acc[2 * ks][1] * inv0);
        __half2 t1 = __floats2half2_rn(acc[2 * ks][2] * inv1, acc[2 * ks][3] * inv1);
        __half2 t2 = __floats2half2_rn(acc[2 * ks + 1][0] * inv0, acc[2 * ks + 1][1] * inv0);
        __half2 t3 = __floats2half2_rn(acc[2 * ks + 1][2] * inv1, acc[2 * ks + 1][3] * inv1);
        pf[ks][0] = *reinterpret_cast<uint32_t*>(&t0);
        pf[ks][1] = *reinterpret_cast<uint32_t*>(&t1);
        pf[ks][2] = *reinterpret_cast<uint32_t*>(&t2);
        pf[ks][3] = *reinterpret_cast<uint32_t*>(&t3);
    }

    // ---- O = P @ V ----
    float oacc[4][4];
    #pragma unroll
    for (int nt = 0; nt < 4; ++nt)
        #pragma unroll
        for (int qq = 0; qq < 4; ++qq) oacc[nt][qq] = 0.f;

    #pragma unroll
    for (int ks = 0; ks < 4; ++ks) {
        uint32_t b[4][2];
        #pragma unroll
        for (int np = 0; np < 2; ++np) {
            uint32_t r4[4];
            ldsm_x4(r4, vb + (uint32_t)((np * 16 + b_nr) * (VT_STRIDE * 2) + (ks * 16 + b_kc) * 2));
            b[np * 2 + 0][0] = r4[0]; b[np * 2 + 0][1] = r4[1];
            b[np * 2 + 1][0] = r4[2]; b[np * 2 + 1][1] = r4[3];
        }
        #pragma unroll
        for (int nt = 0; nt < 4; ++nt)
            mma_f16(oacc[nt], pf[ks], b[nt]);
    }

    #pragma unroll
    for (int nt = 0; nt < 4; ++nt) {
        #pragma unroll
        for (int hh = 0; hh < 2; ++hh) {
            int row = wm + erow + hh * 8;
            if (row >= NTOK) continue;
            int col = nt * 8 + ecol;
            __half2 hp = __floats2half2_rn(oacc[nt][hh * 2 + 0], oacc[nt][hh * 2 + 1]);
            *reinterpret_cast<__half2*>(
                g_ao + ((size_t)w * NTOK + row) * DIM + h * HD + col) = hp;
        }
    }
}

// ---------------- launch ----------------
extern "C" void kernel_launch(void* const* d_in, const int* in_sizes, int n_in,
                              void* d_out, int out_size) {
    const float* x         = (const float*)d_in[0];
    const float* ln1_w     = (const float*)d_in[1];
    const float* ln1_b     = (const float*)d_in[2];
    const float* qkv_w     = (const float*)d_in[3];
    const float* qkv_b     = (const float*)d_in[4];
    const float* proj_w    = (const float*)d_in[5];
    const float* proj_b    = (const float*)d_in[6];
    const float* attn_bias = (const float*)d_in[7];
    const int*   bias_idxs = (const int*)d_in[8];
    const float* conv_w    = (const float*)d_in[9];
    const float* bn_g      = (const float*)d_in[10];
    const float* bn_b      = (const float*)d_in[11];
    const float* bn_m      = (const float*)d_in[12];
    const float* bn_v      = (const float*)d_in[13];
    const float* ln2_w     = (const float*)d_in[14];
    const float* ln2_b     = (const float*)d_in[15];
    const float* fc1_w     = (const float*)d_in[16];
    const float* fc1_b     = (const float*)d_in[17];
    const float* fc2_w     = (const float*)d_in[18];
    const float* fc2_b     = (const float*)d_in[19];
    float* out = (float*)d_out;

    __half *xn, *qkv, *ao, *xn2, *hbuf, *wqh, *wph, *w1h, *w2h;
    float *xa, *xb;
    cudaGetSymbolAddress((void**)&xn,  g_xn);
    cudaGetSymbolAddress((void**)&qkv, g_qkv);
    cudaGetSymbolAddress((void**)&ao,  g_ao);
    cudaGetSymbolAddress((void**)&xa,  g_xa);
    cudaGetSymbolAddress((void**)&xb,  g_xb);
    cudaGetSymbolAddress((void**)&xn2, g_xn2);
    cudaGetSymbolAddress((void**)&hbuf, g_h);
    cudaGetSymbolAddress((void**)&wqh, g_wqh);
    cudaGetSymbolAddress((void**)&wph, g_wph);
    cudaGetSymbolAddress((void**)&w1h, g_w1h);
    cudaGetSymbolAddress((void**)&w2h, g_w2h);

    cudaFuncSetAttribute(hmm_kernel<0>, cudaFuncAttributeMaxDynamicSharedMemorySize, HMM_SMEM_BYTES);
    cudaFuncSetAttribute(hmm_kernel<2>, cudaFuncAttributeMaxDynamicSharedMemorySize, HMM_SMEM_BYTES);
    cudaFuncSetAttribute(hmm64_kernel<1>, cudaFuncAttributeMaxDynamicSharedMemorySize, HMM64_SMEM_BYTES);
    cudaFuncSetAttribute(hmm64_kernel<3>, cudaFuncAttributeMaxDynamicSharedMemorySize, HMM64_SMEM_BYTES);

    // 0) fused prep
    prep_kernel<<<(PREP_TOTAL + 255) / 256, 256>>>(qkv_w, proj_w, fc1_w, fc2_w,
                                                   attn_bias, bias_idxs);

    // 1) LN1 + window partition (fp16)
    ln1_window_kernel<<<TOKENS, 128>>>(x, ln1_w, ln1_b);

    // 2) qkv GEMM (fp16, 128x128)
    {
        dim3 grid((3 * DIM) / 128, MPAD / 128);
        hmm_kernel<0><<<grid, 256, HMM_SMEM_BYTES>>>(xn, wqh, qkv_b, qkv,
                                                     TOKENS, 3 * DIM, DIM);
    }

    // 3) windowed attention
    {
        dim3 grid(NWIN, NH);
        attn_kernel<<<grid, 128>>>();
    }

    // 4) proj GEMM (fp16, 128x64) + fused scatter/residual -> g_xa
    {
        dim3 grid(DIM / 64, MPAD / 128);
        hmm64_kernel<1><<<grid, 256, HMM64_SMEM_BYTES>>>(ao, wph, proj_b, xa, x,
                                                         TOKENS, DIM, DIM);
    }

    // 5) conv + BN + LN2 (fused)
    conv_bn_ln2_kernel<<<BL, 128>>>(conv_w, bn_g, bn_b, bn_m, bn_v, ln2_w, ln2_b);

    // 6) fc1 + gelu (fp16, 128x128)
    {
        dim3 grid(FFN / 128, BL / 128);
        hmm_kernel<2><<<grid, 256, HMM_SMEM_BYTES>>>(xn2, w1h, fc1_b, hbuf,
                                                     BL, FFN, DIM);
    }

    // 7) fc2 + residual -> out (fp16, 128x64)
    {
        dim3 grid(DIM / 64, BL / 128);
        hmm64_kernel<3><<<grid, 256, HMM64_SMEM_BYTES>>>(hbuf, w2h, fc2_b, out, xb,
                                                         BL, DIM, FFN);
    }
}